// round 2
// baseline (speedup 1.0000x reference)
#include <cuda_runtime.h>
#include <math.h>

#define BATCH 4
#define NC 16
#define NF 64
#define VV 262144
#define TOPK 100
#define TILE 64
#define CAND_MAX 4096
#define NBINS 65536
#define THETA 0.9f
#define INV_TAU 10.0f

// ---------------- scratch (device globals; no allocations allowed) ----------------
__device__ float    g_weights[BATCH * VV];        // 4 MB
__device__ unsigned g_hist[BATCH * NBINS];        // 1 MB
__device__ float    g_sums[NC * NF];
__device__ int      g_cnt[NC];
__device__ int      g_thresh[BATCH];
__device__ unsigned g_ccnt[BATCH];
__device__ float    g_cand_val[BATCH * CAND_MAX];
__device__ int      g_cand_idx[BATCH * CAND_MAX];
__device__ int      g_hec[BATCH * TOPK];
__device__ float    g_he[BATCH * TOPK * NF];
__device__ float    g_avg[NC * NF];

// ---------------- init: zero all accumulators + output ----------------
__global__ void kInit(float* out) {
    int gid = blockIdx.x * blockDim.x + threadIdx.x;
    if (gid < BATCH * NBINS) g_hist[gid] = 0u;
    if (gid < NC * NF)       g_sums[gid] = 0.f;
    if (gid < NC)            g_cnt[gid] = 0;
    if (gid < BATCH)         g_ccnt[gid] = 0u;
    if (gid == 0)            out[0] = 0.f;
}

// ---------------- kernel A: labels, per-class counts, per-class feature sums ------
// Tile of 64 voxels. emb tile staged to SMEM transposed [v][f] (stride 65,
// conflict-free). Each warp owns one (voxel, f-half) at a time: the label is
// warp-uniform, so accumulation is a plain SMEM RMW into a warp-private
// [class][lane] table — zero atomics in the hot loop.
__global__ void kA(const float* __restrict__ y, const float* __restrict__ emb) {
    __shared__ float s_emb[TILE][NF + 1];   // 16.6 KB
    __shared__ float s_wacc[8][NC][32];     // 16 KB, warp-private
    __shared__ int   s_lab[TILE];
    __shared__ int   s_cnt[NC];

    int tid  = threadIdx.x;
    int w    = tid >> 5;
    int lane = tid & 31;

    for (int i = tid; i < 8 * NC * 32; i += 256) ((float*)s_wacc)[i] = 0.f;
    if (tid < NC) s_cnt[tid] = 0;
    __syncthreads();

    const int tilesPerB = VV / TILE;            // 4096
    const int nTiles    = BATCH * tilesPerB;    // 16384

    for (int t = blockIdx.x; t < nTiles; t += gridDim.x) {
        int b  = t / tilesPerB;
        int v0 = (t - b * tilesPerB) * TILE;

        // labels for this tile (y is one-hot)
        if (tid < TILE) {
            const float* yp = y + (size_t)b * NC * VV + v0 + tid;
            int lab = 0;
            #pragma unroll
            for (int c = 0; c < NC; c++)
                if (yp[(size_t)c * VV] > 0.5f) lab = c;
            s_lab[tid] = lab;
            atomicAdd(&s_cnt[lab], 1);
        }

        // stage emb tile transposed: s_emb[v][f]
        const float* ep = emb + (size_t)b * NF * VV + v0;
        for (int i = tid; i < NF * TILE; i += 256) {
            int f = i >> 6;        // /TILE
            int j = i & (TILE - 1);
            s_emb[j][f] = ep[(size_t)f * VV + j];  // coalesced over j
        }
        __syncthreads();

        // accumulate: warp w handles f-half (w&1), voxels v = (w>>1) + 4k
        int f = ((w & 1) << 5) + lane;
        for (int v = (w >> 1); v < TILE; v += 4) {
            int lab = s_lab[v];                    // warp-uniform
            s_wacc[w][lab][lane] += s_emb[v][f];   // no atomics, no conflicts
        }
        __syncthreads();
    }

    // flush block-private accumulators
    for (int s = tid; s < NC * NF; s += 256) {
        int c = s >> 6, f = s & 63;
        int half = f >> 5, fl = f & 31;
        float sum = 0.f;
        #pragma unroll
        for (int ww = 0; ww < 4; ww++) sum += s_wacc[half + 2 * ww][c][fl];
        atomicAdd(&g_sums[s], sum);
    }
    if (tid < NC) atomicAdd(&g_cnt[tid], s_cnt[tid]);
}

// ---------------- kernel B: weights = prod_c proba, + 16-bit key histogram -------
__global__ void kB(const float* __restrict__ proba) {
    int gid = blockIdx.x * blockDim.x + threadIdx.x;   // < BATCH*VV
    int b = gid >> 18;
    int v = gid & (VV - 1);
    const float* p = proba + (size_t)b * NC * VV + v;
    float w = 1.f;
    #pragma unroll
    for (int c = 0; c < NC; c++) w *= p[(size_t)c * VV];
    g_weights[gid] = w;
    unsigned key = __float_as_uint(w) >> 16;  // positive floats: monotonic
    atomicAdd(&g_hist[((unsigned)b << 16) | key], 1u);
}

// ---------------- kernel C1: radix-select threshold key per batch ----------------
__global__ void kThresh() {
    int b = blockIdx.x, t = threadIdx.x;   // 256 threads
    const unsigned* h = g_hist + b * NBINS;
    __shared__ unsigned csum[256];
    __shared__ unsigned suf[257];
    unsigned s = 0;
    #pragma unroll 8
    for (int i = 0; i < 256; i++) s += h[t * 256 + i];
    csum[t] = s;
    __syncthreads();
    if (t == 0) {
        unsigned acc = 0; suf[256] = 0;
        for (int i = 255; i >= 0; i--) { acc += csum[i]; suf[i] = acc; }
    }
    __syncthreads();
    if (suf[t] >= TOPK && suf[t + 1] < TOPK) {
        unsigned acc = suf[t + 1];
        int T = t * 256;
        for (int key = t * 256 + 255; key >= t * 256; key--) {
            acc += h[key];
            if (acc >= TOPK) { T = key; break; }
        }
        g_thresh[b] = T;
    }
}

// ---------------- kernel C2: collect candidates >= threshold ---------------------
__global__ void kCollect() {
    int gid = blockIdx.x * blockDim.x + threadIdx.x;
    int b = gid >> 18;
    int v = gid & (VV - 1);
    float w = g_weights[gid];
    unsigned key = __float_as_uint(w) >> 16;
    if ((int)key >= g_thresh[b]) {
        unsigned pos = atomicAdd(&g_ccnt[b], 1u);
        if (pos < CAND_MAX) {
            g_cand_val[b * CAND_MAX + pos] = w;
            g_cand_idx[b * CAND_MAX + pos] = v;
        }
    }
}

// ---------------- kernel C3: exact top-100 by rank, then gather he/hec -----------
__global__ void kSelect(const float* __restrict__ emb, const float* __restrict__ y) {
    int b = blockIdx.x, tid = threadIdx.x;   // 128 threads
    __shared__ float s_val[CAND_MAX];
    __shared__ int   s_idx[CAND_MAX];
    __shared__ int   s_top[TOPK];
    int n = min((int)g_ccnt[b], CAND_MAX);
    for (int i = tid; i < n; i += blockDim.x) {
        s_val[i] = g_cand_val[b * CAND_MAX + i];
        s_idx[i] = g_cand_idx[b * CAND_MAX + i];
    }
    __syncthreads();
    for (int i = tid; i < n; i += blockDim.x) {
        float vi = s_val[i]; int ii = s_idx[i];
        int rank = 0;
        for (int j = 0; j < n; j++) {
            float vj = s_val[j];
            rank += (vj > vi) || (vj == vi && s_idx[j] < ii);  // jax tie-break
        }
        if (rank < TOPK) s_top[rank] = ii;
    }
    __syncthreads();
    // gather hard-example embeddings: he[b,k,f] = emb[b,f,idx]
    for (int t = tid; t < TOPK * NF; t += blockDim.x) {
        int k = t >> 6, f = t & 63;
        int idx = s_top[k];
        g_he[(b * TOPK + k) * NF + f] = emb[((size_t)b * NF + f) * VV + idx];
    }
    // gather labels at selected voxels
    for (int k = tid; k < TOPK; k += blockDim.x) {
        int idx = s_top[k];
        int lab = 0;
        #pragma unroll
        for (int c = 0; c < NC; c++)
            if (y[((size_t)b * NC + c) * VV + idx] > 0.5f) lab = c;
        g_hec[b * TOPK + k] = lab;
    }
}

// ---------------- kernel D: finalize EMA avg --------------------------------------
__global__ void kAvg() {
    int s = blockIdx.x * blockDim.x + threadIdx.x;
    if (s < NC * NF) {
        int c = s >> 6;
        int cnt = g_cnt[c];
        float mean = g_sums[s] / (float)max(cnt, 1);
        g_avg[s] = (cnt > 0) ? THETA * mean : 0.f;
    }
}

// ---------------- kernel E: contrastive pair loss, one block per (b, class) ------
// F=64 split into two 32-wide chunks so total shared stays under 48 KB
// (no dynamic shared, no cudaFuncSetAttribute needed).
#define FCH 32
__global__ void kLoss(float* out) {
    int b  = blockIdx.x >> 4;
    int cc = blockIdx.x & 15;
    int tid = threadIdx.x;   // 256

    __shared__ float s_l[TOPK * FCH];    // logits for class cc, this f-chunk (12.8 KB)
    __shared__ float s_N[TOPK * FCH];    // S_j - E_j(cc), this f-chunk       (12.8 KB)
    __shared__ float s_avg[NC * NF];     // 4 KB
    __shared__ int   s_mem[TOPK];
    __shared__ int   s_m;
    __shared__ float s_red[256];

    if (tid == 0) s_m = 0;
    for (int i = tid; i < NC * NF; i += 256) s_avg[i] = g_avg[i];
    __syncthreads();

    for (int k = tid; k < TOPK; k += 256)
        if (g_hec[b * TOPK + k] == cc) { int p = atomicAdd(&s_m, 1); s_mem[p] = k; }
    __syncthreads();
    int m = s_m;
    if (m == 0) return;   // uniform exit

    float local = 0.f;
    int npairs = m * m;

    #pragma unroll
    for (int fc = 0; fc < NF / FCH; fc++) {
        int f0 = fc * FCH;

        // per-member, this f-chunk: l_c and N = sum_{c'} exp(l_{c'}) - exp(l_c)
        for (int idx = tid; idx < m * FCH; idx += 256) {
            int j = idx >> 5, f = (idx & (FCH - 1)) + f0;
            float he = g_he[(b * TOPK + s_mem[j]) * NF + f];
            float S = 0.f, lc = 0.f, ec = 1.f;
            #pragma unroll
            for (int c2 = 0; c2 < NC; c2++) {
                float l = he * s_avg[c2 * NF + f] * INV_TAU;
                float e = expf(l);
                S += e;
                if (c2 == cc) { lc = l; ec = e; }
            }
            s_l[idx] = lc;
            s_N[idx] = S - ec;
        }
        __syncthreads();

        for (int p = tid; p < npairs; p += 256) {
            int i = p / m;
            int j = p - i * m;
            const float* li = s_l + i * FCH;
            const float* Nj = s_N + j * FCH;
            #pragma unroll 8
            for (int f = 0; f < FCH; f++) {
                float l = li[f];
                local += logf(expf(l) + Nj[f]) - l;
            }
        }
        __syncthreads();
    }

    s_red[tid] = local;
    __syncthreads();
    for (int s = 128; s > 0; s >>= 1) {
        if (tid < s) s_red[tid] += s_red[tid + s];
        __syncthreads();
    }
    if (tid == 0) {
        float denom = (float)m * (float)m * (float)NF;
        atomicAdd(out, -(s_red[0] / denom) / (float)BATCH);
    }
}

// ---------------- launch ----------------------------------------------------------
extern "C" void kernel_launch(void* const* d_in, const int* in_sizes, int n_in,
                              void* d_out, int out_size) {
    const float* proba = (const float*)d_in[0];
    const float* y     = (const float*)d_in[1];
    const float* emb   = (const float*)d_in[2];
    float* out = (float*)d_out;
    (void)in_sizes; (void)n_in; (void)out_size;

    kInit<<<(BATCH * NBINS + 255) / 256, 256>>>(out);
    kA<<<888, 256>>>(y, emb);
    kB<<<BATCH * VV / 256, 256>>>(proba);
    kThresh<<<BATCH, 256>>>();
    kCollect<<<BATCH * VV / 256, 256>>>();
    kSelect<<<BATCH, 128>>>(emb, y);
    kAvg<<<(NC * NF + 255) / 256, 256>>>();
    kLoss<<<BATCH * NC, 256>>>(out);
}

// round 4
// speedup vs baseline: 1.5209x; 1.5209x over previous
#include <cuda_runtime.h>
#include <math.h>

#define BATCH 4
#define NC 16
#define NF 64
#define VV 262144
#define TOPK 100
#define TILE 64
#define CAND_MAX 4096
#define NBINS 65536
#define THETA 0.9f
#define INV_TAU 10.0f

#define GA 888    // kA-part blocks in fused kernel
#define GB 1024   // kB-part blocks (1024*256*4 = BATCH*VV elements)

// ---------------- scratch (device globals; no allocations allowed) ----------------
__device__ float    g_weights[BATCH * VV];        // 4 MB
__device__ unsigned g_hist[BATCH * NBINS];        // 1 MB
__device__ float    g_sums[NC * NF];
__device__ int      g_cnt[NC];
__device__ int      g_thresh[BATCH];
__device__ unsigned g_ccnt[BATCH];
__device__ float    g_cand_val[BATCH * CAND_MAX];
__device__ int      g_cand_idx[BATCH * CAND_MAX];
__device__ int      g_hec[BATCH * TOPK];
__device__ float    g_he[BATCH * TOPK * NF];

// ---------------- init: zero all accumulators + output ----------------
__global__ void kInit(float* out) {
    int gid = blockIdx.x * blockDim.x + threadIdx.x;   // 65536 threads
    ((uint4*)g_hist)[gid] = make_uint4(0u, 0u, 0u, 0u);
    if (gid < NC * NF) g_sums[gid] = 0.f;
    if (gid < NC)      g_cnt[gid] = 0;
    if (gid < BATCH)   g_ccnt[gid] = 0u;
    if (gid == 0)      out[0] = 0.f;
}

// ---------------- fused kernel AB ------------------------------------------------
// blocks [0, GA):   per-class feature sums + counts (kA)
// blocks [GA, +GB): weights = prod_c proba + 16-bit key histogram (kB)
__global__ void kAB(const float* __restrict__ y, const float* __restrict__ emb,
                    const float* __restrict__ proba) {
    __shared__ float s_emb[TILE][NF + 1];   // [v][f], stride 65: accumulate LDS conflict-free
    __shared__ float s_wacc[8][NC][32];     // warp-private accumulators
    __shared__ int   s_lab[TILE];
    __shared__ int   s_cnt[NC];

    int tid = threadIdx.x;

    if (blockIdx.x >= GA) {
        // ---- kB part: pure streaming ----
        int gid = (blockIdx.x - GA) * 256 + tid;   // 0..262143
        int b = gid >> 16;
        int r = gid & 65535;
        int v0 = r << 2;
        const float4* p4 = (const float4*)(proba + ((size_t)b * NC << 18) + v0);
        float4 acc = make_float4(1.f, 1.f, 1.f, 1.f);
        #pragma unroll
        for (int c = 0; c < NC; c++) {
            float4 p = p4[(size_t)c * (VV / 4)];
            acc.x *= p.x; acc.y *= p.y; acc.z *= p.z; acc.w *= p.w;
        }
        *(float4*)(g_weights + ((size_t)b << 18) + v0) = acc;
        unsigned base = (unsigned)b << 16;
        atomicAdd(&g_hist[base | (__float_as_uint(acc.x) >> 16)], 1u);
        atomicAdd(&g_hist[base | (__float_as_uint(acc.y) >> 16)], 1u);
        atomicAdd(&g_hist[base | (__float_as_uint(acc.z) >> 16)], 1u);
        atomicAdd(&g_hist[base | (__float_as_uint(acc.w) >> 16)], 1u);
        return;
    }

    // ---- kA part ----
    int w    = tid >> 5;
    int lane = tid & 31;

    for (int i = tid; i < 8 * NC * 32; i += 256) ((float*)s_wacc)[i] = 0.f;
    if (tid < NC) s_cnt[tid] = 0;
    __syncthreads();

    const int tilesPerB = VV / TILE;            // 4096
    const int nTiles    = BATCH * tilesPerB;    // 16384

    // y-read mapping: thread = (class c, v4-group); one LDG.128 per thread per tile
    int yc  = tid >> 4;        // 0..15
    int yv4 = tid & 15;        // 0..15

    for (int t = blockIdx.x; t < nTiles; t += GA) {
        int b  = t / tilesPerB;
        int v0 = (t - b * tilesPerB) * TILE;

        // labels: one-hot scan, vectorized (exactly one thread writes each s_lab[v])
        {
            float4 yy = *(const float4*)(y + ((size_t)b * NC + yc) * VV + v0 + (yv4 << 2));
            int hits = 0;
            if (yy.x > 0.5f) { s_lab[(yv4 << 2) + 0] = yc; hits++; }
            if (yy.y > 0.5f) { s_lab[(yv4 << 2) + 1] = yc; hits++; }
            if (yy.z > 0.5f) { s_lab[(yv4 << 2) + 2] = yc; hits++; }
            if (yy.w > 0.5f) { s_lab[(yv4 << 2) + 3] = yc; hits++; }
            if (hits) atomicAdd(&s_cnt[yc], hits);
        }

        // stage emb tile transposed: s_emb[v][f], LDG.128 along v, 4 scalar STS
        const float4* ep4 = (const float4*)(emb + (size_t)b * NF * VV + v0);
        #pragma unroll
        for (int rr = 0; rr < 4; rr++) {
            int q  = tid + (rr << 8);        // 0..1023
            int f  = q >> 4;
            int j  = (q & 15) << 2;
            float4 val = ep4[(size_t)f * (VV / 4) + (q & 15)];
            s_emb[j + 0][f] = val.x;
            s_emb[j + 1][f] = val.y;
            s_emb[j + 2][f] = val.z;
            s_emb[j + 3][f] = val.w;
        }
        __syncthreads();

        // accumulate: warp w -> f-half (w&1), voxels v = (w>>1) + 4k; label warp-uniform
        int f = ((w & 1) << 5) + lane;
        #pragma unroll
        for (int v = (w >> 1); v < TILE; v += 4) {
            int lab = s_lab[v];
            s_wacc[w][lab][lane] += s_emb[v][f];
        }
        __syncthreads();
    }

    // flush block-private accumulators
    for (int s = tid; s < NC * NF; s += 256) {
        int c = s >> 6, f = s & 63;
        int half = f >> 5, fl = f & 31;
        float sum = 0.f;
        #pragma unroll
        for (int ww = 0; ww < 4; ww++) sum += s_wacc[half + 2 * ww][c][fl];
        atomicAdd(&g_sums[s], sum);
    }
    if (tid < NC) atomicAdd(&g_cnt[tid], s_cnt[tid]);
}

// ---------------- kThresh: radix-select threshold key, 1024 threads/batch --------
// Low-register version: pass 1 streams bins (sum only), suffix scan in SMEM,
// single winner thread re-reads its 64 bins (L2-hot) to locate exact key.
__global__ void __launch_bounds__(1024) kThresh() {
    int b = blockIdx.x, t = threadIdx.x;    // 1024 threads
    const uint4* h4 = (const uint4*)(g_hist + b * NBINS);

    unsigned s = 0;
    #pragma unroll
    for (int i = 0; i < 16; i++) {
        uint4 v = h4[t * 16 + i];   // bins [64t, 64t+64)
        s += v.x + v.y + v.z + v.w;
    }

    __shared__ unsigned suf[1025];
    suf[t] = s;
    if (t == 0) suf[1024] = 0;
    __syncthreads();

    // Hillis-Steele inclusive suffix scan
    #pragma unroll
    for (int off = 1; off < 1024; off <<= 1) {
        unsigned add = (t + off < 1024) ? suf[t + off] : 0u;
        __syncthreads();
        suf[t] += add;
        __syncthreads();
    }

    if (suf[t] >= TOPK && suf[t + 1] < TOPK) {
        // winner thread: re-read own 64 bins (L2-hot) descending
        unsigned run = suf[t + 1];
        const unsigned* h = g_hist + b * NBINS + t * 64;
        int T = t * 64;
        for (int i = 63; i >= 0; i--) {
            run += h[i];
            if (run >= TOPK) { T = t * 64 + i; break; }
        }
        g_thresh[b] = T;
    }
}

// ---------------- kCollect: candidates >= threshold (vectorized) -----------------
__global__ void kCollect() {
    int gid = blockIdx.x * 256 + threadIdx.x;   // 262144
    int b = gid >> 16;
    int r = gid & 65535;
    int v0 = r << 2;
    float4 w4 = *(const float4*)(g_weights + ((size_t)b << 18) + v0);
    int th = g_thresh[b];
    float wv[4] = {w4.x, w4.y, w4.z, w4.w};
    #pragma unroll
    for (int k = 0; k < 4; k++) {
        if ((int)(__float_as_uint(wv[k]) >> 16) >= th) {
            unsigned pos = atomicAdd(&g_ccnt[b], 1u);
            if (pos < CAND_MAX) {
                g_cand_val[b * CAND_MAX + pos] = wv[k];
                g_cand_idx[b * CAND_MAX + pos] = v0 + k;
            }
        }
    }
}

// ---------------- kSelect: exact top-100 by rank, gather he/hec ------------------
__global__ void kSelect(const float* __restrict__ emb, const float* __restrict__ y) {
    int b = blockIdx.x, tid = threadIdx.x;   // 128 threads
    __shared__ float s_val[CAND_MAX];
    __shared__ int   s_idx[CAND_MAX];
    __shared__ int   s_top[TOPK];
    int n = min((int)g_ccnt[b], CAND_MAX);
    for (int i = tid; i < n; i += blockDim.x) {
        s_val[i] = g_cand_val[b * CAND_MAX + i];
        s_idx[i] = g_cand_idx[b * CAND_MAX + i];
    }
    __syncthreads();
    for (int i = tid; i < n; i += blockDim.x) {
        float vi = s_val[i]; int ii = s_idx[i];
        int rank = 0;
        for (int j = 0; j < n; j++) {
            float vj = s_val[j];
            rank += (vj > vi) || (vj == vi && s_idx[j] < ii);  // jax tie-break
        }
        if (rank < TOPK) s_top[rank] = ii;
    }
    __syncthreads();
    for (int t = tid; t < TOPK * NF; t += blockDim.x) {
        int k = t >> 6, f = t & 63;
        int idx = s_top[k];
        g_he[(b * TOPK + k) * NF + f] = emb[((size_t)b * NF + f) * VV + idx];
    }
    for (int k = tid; k < TOPK; k += blockDim.x) {
        int idx = s_top[k];
        int lab = 0;
        #pragma unroll
        for (int c = 0; c < NC; c++)
            if (y[((size_t)b * NC + c) * VV + idx] > 0.5f) lab = c;
        g_hec[b * TOPK + k] = lab;
    }
}

// ---------------- kLoss: contrastive pair loss, one block per (b, class) ---------
// Computes EMA avg inline from g_sums/g_cnt. F split into two 32-chunks -> <48KB.
#define FCH 32
__global__ void kLoss(float* out) {
    int b  = blockIdx.x >> 4;
    int cc = blockIdx.x & 15;
    int tid = threadIdx.x;   // 256

    __shared__ float s_l[TOPK * FCH];    // 12.8 KB
    __shared__ float s_N[TOPK * FCH];    // 12.8 KB
    __shared__ float s_avg[NC * NF];     // 4 KB
    __shared__ int   s_mem[TOPK];
    __shared__ int   s_m;
    __shared__ float s_red[256];

    if (tid == 0) s_m = 0;
    for (int i = tid; i < NC * NF; i += 256) {
        int c = i >> 6;
        int cnt = g_cnt[c];
        float mean = g_sums[i] / (float)max(cnt, 1);
        s_avg[i] = (cnt > 0) ? THETA * mean : 0.f;
    }
    __syncthreads();

    for (int k = tid; k < TOPK; k += 256)
        if (g_hec[b * TOPK + k] == cc) { int p = atomicAdd(&s_m, 1); s_mem[p] = k; }
    __syncthreads();
    int m = s_m;
    if (m == 0) return;   // uniform exit

    float local = 0.f;
    int npairs = m * m;

    #pragma unroll
    for (int fc = 0; fc < NF / FCH; fc++) {
        int f0 = fc * FCH;

        for (int idx = tid; idx < m * FCH; idx += 256) {
            int j = idx >> 5, f = (idx & (FCH - 1)) + f0;
            float he = g_he[(b * TOPK + s_mem[j]) * NF + f];
            float S = 0.f, lc = 0.f, ec = 1.f;
            #pragma unroll
            for (int c2 = 0; c2 < NC; c2++) {
                float l = he * s_avg[c2 * NF + f] * INV_TAU;
                float e = expf(l);
                S += e;
                if (c2 == cc) { lc = l; ec = e; }
            }
            s_l[idx] = lc;
            s_N[idx] = S - ec;
        }
        __syncthreads();

        for (int p = tid; p < npairs; p += 256) {
            int i = p / m;
            int j = p - i * m;
            const float* li = s_l + i * FCH;
            const float* Nj = s_N + j * FCH;
            #pragma unroll 8
            for (int f = 0; f < FCH; f++) {
                float l = li[f];
                local += logf(expf(l) + Nj[f]) - l;
            }
        }
        __syncthreads();
    }

    s_red[tid] = local;
    __syncthreads();
    for (int s = 128; s > 0; s >>= 1) {
        if (tid < s) s_red[tid] += s_red[tid + s];
        __syncthreads();
    }
    if (tid == 0) {
        float denom = (float)m * (float)m * (float)NF;
        atomicAdd(out, -(s_red[0] / denom) / (float)BATCH);
    }
}

// ---------------- launch ----------------------------------------------------------
extern "C" void kernel_launch(void* const* d_in, const int* in_sizes, int n_in,
                              void* d_out, int out_size) {
    const float* proba = (const float*)d_in[0];
    const float* y     = (const float*)d_in[1];
    const float* emb   = (const float*)d_in[2];
    float* out = (float*)d_out;
    (void)in_sizes; (void)n_in; (void)out_size;

    kInit<<<256, 256>>>(out);
    kAB<<<GA + GB, 256>>>(y, emb, proba);
    kThresh<<<BATCH, 1024>>>();
    kCollect<<<1024, 256>>>();
    kSelect<<<BATCH, 128>>>(emb, y);
    kLoss<<<BATCH * NC, 256>>>(out);
}